// round 11
// baseline (speedup 1.0000x reference)
#include <cuda_runtime.h>
#include <cstdint>

#define NUM_E      5
#define NTOK       (16 * 2048)
#define OUTF       512
#define MAXF       128
#define BM         64
#define MAX_ROWS   (NTOK + NUM_E * BM)
#define MAX_MTILES (MAX_ROWS / BM)
#define WTOT       (NUM_E * OUTF * MAXF)
// worst smem: K=128: A hi/lo 2*64*136 + B 1 buf * 2 planes * 32*136  (floats)
#define SMEM_BYTES ((2 * 64 * 136 + 2 * 32 * 136) * 4)

// ---------------- scratch (static device globals; zero-initialized at load) ---------------
__device__ int   g_counts[NUM_E];
__device__ int   g_offsets[NUM_E + 1];
__device__ int   g_slot[NTOK];
__device__ int   g_rows[MAX_ROWS];          // gathered row -> token id (-1 = padding)
__device__ float g_wh[WTOT];                // weights pre-split to tf32 hi/lo, k-permuted
__device__ float g_wl[WTOT];

// in_feat_size may be int32 or int64. Values in {8,16,32,64,128}; if int64, word[1]==0.
__device__ __forceinline__ int expert_of(const int* __restrict__ feat, int t) {
    int is64 = (feat[1] == 0) ? 1 : 0;
    int v = feat[is64 ? (t << 1) : t];
    return __ffs(v) - 4;   // 8->0 ... 128->4
}

__global__ void k_count(const int* __restrict__ feat) {
    int t = blockIdx.x * blockDim.x + threadIdx.x;
    if (t >= NTOK) return;
    int e = expert_of(feat, t);
    unsigned m = __match_any_sync(0xffffffffu, e);
    int lane   = threadIdx.x & 31;
    int leader = __ffs(m) - 1;
    int rank   = __popc(m & ((1u << lane) - 1u));
    int base   = 0;
    if (lane == leader) base = atomicAdd(&g_counts[e], __popc(m));
    base = __shfl_sync(0xffffffffu, base, leader);
    g_slot[t] = base + rank;
}

__global__ void k_offsets() {
    if (threadIdx.x == 0) {
        int acc = 0;
        for (int e = 0; e < NUM_E; e++) {
            g_offsets[e] = acc;
            acc += (g_counts[e] + BM - 1) / BM * BM;
        }
        g_offsets[NUM_E] = acc;
    }
    __syncthreads();
    for (int e = 0; e < NUM_E; e++) {
        int s  = g_offsets[e] + g_counts[e];
        int en = g_offsets[e + 1];
        for (int i = s + (int)threadIdx.x; i < en; i += blockDim.x) g_rows[i] = -1;
    }
    __syncthreads();
    if (threadIdx.x < NUM_E) g_counts[threadIdx.x] = 0;   // reset for next graph replay
}

__global__ void k_scatter(const int* __restrict__ feat) {
    int t = blockIdx.x * blockDim.x + threadIdx.x;
    if (t >= NTOK) return;
    int e = expert_of(feat, t);
    g_rows[g_offsets[e] + g_slot[t]] = t;
}

// ---------------- 3xTF32 helpers ----------------
__device__ __forceinline__ void split_tf32(float f, uint32_t& hi, uint32_t& lo) {
    asm("cvt.rna.tf32.f32 %0, %1;" : "=r"(hi) : "f"(f));
    float lf = f - __uint_as_float(hi);
    asm("cvt.rna.tf32.f32 %0, %1;" : "=r"(lo) : "f"(lf));
}

// k-permutation: (b[k], b[k+4]) / (a[k], a[k+4]) become adjacent -> LDS.64 pairs
__device__ __forceinline__ int permk(int k) {
    return (k & ~7) | ((k & 3) << 1) | ((k >> 2) & 1);
}

__global__ void k_wsplit(const float* __restrict__ w) {
    int i = blockIdx.x * blockDim.x + threadIdx.x;
    if (i >= WTOT) return;
    uint32_t hi, lo;
    split_tf32(w[i], hi, lo);
    int d = (i & ~(MAXF - 1)) | permk(i & (MAXF - 1));
    g_wh[d] = __uint_as_float(hi);
    g_wl[d] = __uint_as_float(lo);
}

__device__ __forceinline__ void mma8(float* c, const uint32_t* a, const uint32_t* b) {
    asm volatile(
        "mma.sync.aligned.m16n8k8.row.col.f32.tf32.tf32.f32 "
        "{%0,%1,%2,%3}, {%4,%5,%6,%7}, {%8,%9}, {%0,%1,%2,%3};\n"
        : "+f"(c[0]), "+f"(c[1]), "+f"(c[2]), "+f"(c[3])
        : "r"(a[0]), "r"(a[1]), "r"(a[2]), "r"(a[3]), "r"(b[0]), "r"(b[1]));
}

__device__ __forceinline__ void cpa16(void* sptr, const void* gptr) {
    uint32_t s = (uint32_t)__cvta_generic_to_shared(sptr);
    asm volatile("cp.async.cg.shared.global [%0], [%1], 16;\n" :: "r"(s), "l"(gptr) : "memory");
}
#define CP_COMMIT() asm volatile("cp.async.commit_group;\n" ::: "memory")
#define CP_WAIT0()  asm volatile("cp.async.wait_group 0;\n" ::: "memory")
#define CP_WAIT1()  asm volatile("cp.async.wait_group 1;\n" ::: "memory")

// ---------------- templated expert GEMM --------------------------------------------------
// BM=64 rows. 8 warps = 4 over M x 2 over N; each warp one m16 tile x NF n8 tiles.
// B is pre-split (hi/lo planes, k-permuted) in global -> smem via cp.async; NO runtime
// B splits. AREG (K<=32): A split to registers once. Otherwise A split once per block
// into k-permuted hi/lo smem; inner loop A access = 2x LDS.64 per half.
template <int K, bool AREG, int BN>
__device__ __forceinline__ void gemm_expert(
    int row0,
    const float* __restrict__ x,
    const float* __restrict__ wh,    // g_wh + e*OUTF*MAXF
    const float* __restrict__ wl,
    const float* __restrict__ be,
    float* __restrict__ out,
    float* sm)
{
    constexpr int  ldsA = AREG ? (K + 4) : (K + 8);   // scalar-read vs LDS.64-read strides
    constexpr int  ldsB = (K <= 16) ? 24 : (K + 8);   // ldsB % 32 in {24, 8}: conflict-free LDS.64
    constexpr int  kq   = K >> 2;
    constexpr int  KS   = K / 8;
    constexpr int  NT   = OUTF / BN;
    constexpr int  NF   = BN / 16;                    // n8 frags per warp (2 N-warps)
    constexpr bool DB   = (K <= 64);                  // double-buffered B
    constexpr int  LOGK = (K == 8) ? 3 : (K == 16) ? 4 : (K == 32) ? 5 : (K == 64) ? 6 : 7;
    constexpr int  BUFS = DB ? 2 : 1;
    constexpr int  BSZ  = 2 * BN * ldsB;              // hi+lo planes per buffer (floats)

    float* sA  = sm;                                  // AREG: raw [BM][ldsA]; else hi [BM][ldsA]
    float* sAl = sm + BM * ldsA;                      // (non-AREG only) lo plane
    float* sB  = sm + (AREG ? 1 : 2) * BM * ldsA;     // BUFS x (hi plane, lo plane)

    const int tx = threadIdx.x;

    // ---- B tile loader: copies pre-split hi+lo rows (already k-permuted) ----
    auto load_B = [&](float* buf, int nt) {
        const size_t nb = (size_t)nt * BN;
        #pragma unroll
        for (int i = tx; i < BN * kq; i += 256) {
            int r = i / kq, c = (i % kq) << 2;
            cpa16(buf + r * ldsB + c,             wh + (nb + r) * MAXF + c);
            cpa16(buf + BN * ldsB + r * ldsB + c, wl + (nb + r) * MAXF + c);
        }
    };

    // ---- prologue ----
    if (AREG) {
        // group0: raw A + B(0); group1: B(1)
        #pragma unroll
        for (int i = tx; i < BM * kq; i += 256) {
            int r = i / kq, c = (i % kq) << 2;
            int tok = g_rows[row0 + r];
            tok = tok < 0 ? 0 : tok;
            cpa16(sA + r * ldsA + c, x + (size_t)tok * MAXF + c);
        }
        load_B(sB, 0);
        CP_COMMIT();
        load_B(sB + BSZ, 1);
        CP_COMMIT();
    } else {
        // stage raw A in the B region, split to permuted hi/lo smem, then start B
        #pragma unroll
        for (int i = tx; i < BM * kq; i += 256) {
            int r = i / kq, c = (i % kq) << 2;
            int tok = g_rows[row0 + r];
            tok = tok < 0 ? 0 : tok;
            cpa16(sB + r * K + c, x + (size_t)tok * MAXF + c);
        }
        CP_COMMIT();
        CP_WAIT0();
        __syncthreads();
        #pragma unroll 4
        for (int i = tx; i < BM * K; i += 256) {
            int r = i >> LOGK, k = i & (K - 1);
            uint32_t hi, lo;
            split_tf32(sB[r * K + k], hi, lo);
            int p = permk(k);
            sA [r * ldsA + p] = __uint_as_float(hi);
            sAl[r * ldsA + p] = __uint_as_float(lo);
        }
        __syncthreads();
        load_B(sB, 0);
        CP_COMMIT();
        if (DB) { load_B(sB + BSZ, 1); CP_COMMIT(); }
    }

    const int warp = tx >> 5, lane = tx & 31;
    const int wm = warp & 3, wn = warp >> 2;          // 4 M-warps x 2 N-warps
    const int grp = lane >> 2, qid = lane & 3;

    const int t0 = g_rows[row0 + wm * 16 + grp];
    const int t1 = g_rows[row0 + wm * 16 + grp + 8];

    uint32_t rah[AREG ? KS : 1][4], ral[AREG ? KS : 1][4];
    const float* aH = sA  + (wm * 16 + grp) * ldsA + qid * 2;  // non-AREG LDS.64 base
    const float* aL = sAl + (wm * 16 + grp) * ldsA + qid * 2;

    for (int nt = 0; nt < NT; nt++) {
        if (DB) CP_WAIT1(); else CP_WAIT0();
        __syncthreads();
        const float* sBuf = DB ? (sB + (nt & 1) * BSZ) : sB;

        if (AREG && nt == 0) {
            const float* ap = sA + (wm * 16 + grp) * ldsA + qid;
            #pragma unroll
            for (int ks = 0; ks < KS; ks++) {
                split_tf32(ap[ks * 8],                rah[ks][0], ral[ks][0]);
                split_tf32(ap[ks * 8 + 8 * ldsA],     rah[ks][1], ral[ks][1]);
                split_tf32(ap[ks * 8 + 4],            rah[ks][2], ral[ks][2]);
                split_tf32(ap[ks * 8 + 8 * ldsA + 4], rah[ks][3], ral[ks][3]);
            }
        }

        // split accumulators -> independent MMA chains
        float c_hh[NF][4] = {}, c_lh[NF][4] = {}, c_hl[NF][4] = {};

        #pragma unroll
        for (int ks = 0; ks < KS; ks++) {
            uint32_t ah[4], al[4];
            if (AREG) {
                #pragma unroll
                for (int j = 0; j < 4; j++) { ah[j] = rah[ks][j]; al[j] = ral[ks][j]; }
            } else {
                uint2 h0 = *(const uint2*)(aH + ks * 8);
                uint2 h1 = *(const uint2*)(aH + ks * 8 + 8 * ldsA);
                uint2 l0 = *(const uint2*)(aL + ks * 8);
                uint2 l1 = *(const uint2*)(aL + ks * 8 + 8 * ldsA);
                ah[0] = h0.x; ah[1] = h1.x; ah[2] = h0.y; ah[3] = h1.y;
                al[0] = l0.x; al[1] = l1.x; al[2] = l0.y; al[3] = l1.y;
            }
            #pragma unroll
            for (int nf = 0; nf < NF; nf++) {
                const float* bp = sBuf + (wn * (BN / 2) + nf * 8 + grp) * ldsB + ks * 8 + qid * 2;
                uint2 bh2 = *(const uint2*)bp;
                uint2 bl2 = *(const uint2*)(bp + BN * ldsB);
                uint32_t bh[2] = {bh2.x, bh2.y};
                uint32_t bl[2] = {bl2.x, bl2.y};
                mma8(c_hh[nf], ah, bh);
                mma8(c_lh[nf], al, bh);
                mma8(c_hl[nf], ah, bl);
            }
        }

        // ---- scatter epilogue: merge partial sums + bias ----
        const int n0 = nt * BN + wn * (BN / 2);
        #pragma unroll
        for (int nf = 0; nf < NF; nf++) {
            int c = n0 + nf * 8 + (qid << 1);
            float2 bv = *(const float2*)(be + c);
            if (t0 >= 0) {
                float2 o = make_float2(c_hh[nf][0] + c_lh[nf][0] + c_hl[nf][0] + bv.x,
                                       c_hh[nf][1] + c_lh[nf][1] + c_hl[nf][1] + bv.y);
                *(float2*)(out + (size_t)t0 * OUTF + c) = o;
            }
            if (t1 >= 0) {
                float2 o = make_float2(c_hh[nf][2] + c_lh[nf][2] + c_hl[nf][2] + bv.x,
                                       c_hh[nf][3] + c_lh[nf][3] + c_hl[nf][3] + bv.y);
                *(float2*)(out + (size_t)t1 * OUTF + c) = o;
            }
        }

        __syncthreads();
        if (DB) {
            if (nt + 2 < NT) load_B(sB + (nt & 1) * BSZ, nt + 2);
            CP_COMMIT();                              // keep wait_group(1) invariant
        } else {
            if (nt + 1 < NT) { load_B(sB, nt + 1); CP_COMMIT(); }
        }
    }
}

__global__ void __launch_bounds__(256, 2)
k_gemm(const float* __restrict__ x, const float* __restrict__ bias, float* __restrict__ out) {
    extern __shared__ float sm[];
    // reversed order: heavy K=128 blocks (highest rows) scheduled FIRST
    const int total = g_offsets[NUM_E];
    const int row0  = total - (int)(blockIdx.x + 1) * BM;
    if (row0 < 0) return;

    int e = 0;
    #pragma unroll
    for (int i = 1; i < NUM_E; i++) e += (row0 >= g_offsets[i]);

    const float* wh = g_wh + (size_t)e * OUTF * MAXF;
    const float* wl = g_wl + (size_t)e * OUTF * MAXF;
    const float* be = bias + e * OUTF;

    switch (e) {
        case 0:  gemm_expert<  8, true,  64>(row0, x, wh, wl, be, out, sm); break;
        case 1:  gemm_expert< 16, true,  64>(row0, x, wh, wl, be, out, sm); break;
        case 2:  gemm_expert< 32, true,  64>(row0, x, wh, wl, be, out, sm); break;
        case 3:  gemm_expert< 64, false, 32>(row0, x, wh, wl, be, out, sm); break;
        default: gemm_expert<128, false, 32>(row0, x, wh, wl, be, out, sm); break;
    }
}

// ---------------- launch ----------------
extern "C" void kernel_launch(void* const* d_in, const int* in_sizes, int n_in,
                              void* d_out, int out_size) {
    (void)in_sizes; (void)n_in; (void)out_size;
    const float* x    = (const float*)d_in[0];
    const int*   feat = (const int*)d_in[1];
    const float* w    = (const float*)d_in[2];
    const float* b    = (const float*)d_in[3];
    float*       out  = (float*)d_out;

    cudaFuncSetAttribute(k_gemm, cudaFuncAttributeMaxDynamicSharedMemorySize, SMEM_BYTES);

    k_wsplit <<<(WTOT + 255) / 256, 256>>>(w);
    k_count  <<<(NTOK + 255) / 256, 256>>>(feat);
    k_offsets<<<1, 256>>>();
    k_scatter<<<(NTOK + 255) / 256, 256>>>(feat);
    k_gemm   <<<MAX_MTILES, 256, SMEM_BYTES>>>(x, b, out);
}

// round 12
// speedup vs baseline: 1.0050x; 1.0050x over previous
#include <cuda_runtime.h>
#include <cstdint>

#define NUM_E      5
#define NTOK       (16 * 2048)
#define OUTF       512
#define MAXF       128
#define BM         64
#define MAX_ROWS   (NTOK + NUM_E * BM)
#define MAX_MTILES (MAX_ROWS / BM)
#define WTOT       (NUM_E * OUTF * MAXF)
// worst smem: K=128: A hi/lo 2*64*136 + B 1 buf * 2 planes * 32*136  (floats)
#define SMEM_BYTES ((2 * 64 * 136 + 2 * 32 * 136) * 4)

// ---------------- scratch (static device globals; zero-initialized at load) ---------------
__device__ int   g_counts[NUM_E];
__device__ int   g_offsets[NUM_E + 1];
__device__ int   g_slot[NTOK];
__device__ int   g_rows[MAX_ROWS];          // gathered row -> token id (-1 = padding)
__device__ float g_wh[WTOT];                // weights pre-split to tf32 hi/lo, k-permuted
__device__ float g_wl[WTOT];

// in_feat_size may be int32 or int64. Values in {8,16,32,64,128}; if int64, word[1]==0.
__device__ __forceinline__ int expert_of(const int* __restrict__ feat, int t) {
    int is64 = (feat[1] == 0) ? 1 : 0;
    int v = feat[is64 ? (t << 1) : t];
    return __ffs(v) - 4;   // 8->0 ... 128->4
}

__global__ void k_count(const int* __restrict__ feat) {
    int t = blockIdx.x * blockDim.x + threadIdx.x;
    if (t >= NTOK) return;
    int e = expert_of(feat, t);
    unsigned m = __match_any_sync(0xffffffffu, e);
    int lane   = threadIdx.x & 31;
    int leader = __ffs(m) - 1;
    int rank   = __popc(m & ((1u << lane) - 1u));
    int base   = 0;
    if (lane == leader) base = atomicAdd(&g_counts[e], __popc(m));
    base = __shfl_sync(0xffffffffu, base, leader);
    g_slot[t] = base + rank;
}

__global__ void k_offsets() {
    if (threadIdx.x == 0) {
        int acc = 0;
        for (int e = 0; e < NUM_E; e++) {
            g_offsets[e] = acc;
            acc += (g_counts[e] + BM - 1) / BM * BM;
        }
        g_offsets[NUM_E] = acc;
    }
    __syncthreads();
    for (int e = 0; e < NUM_E; e++) {
        int s  = g_offsets[e] + g_counts[e];
        int en = g_offsets[e + 1];
        for (int i = s + (int)threadIdx.x; i < en; i += blockDim.x) g_rows[i] = -1;
    }
    __syncthreads();
    if (threadIdx.x < NUM_E) g_counts[threadIdx.x] = 0;   // reset for next graph replay
}

__global__ void k_scatter(const int* __restrict__ feat) {
    int t = blockIdx.x * blockDim.x + threadIdx.x;
    if (t >= NTOK) return;
    int e = expert_of(feat, t);
    g_rows[g_offsets[e] + g_slot[t]] = t;
}

// ---------------- 3xTF32 helpers ----------------
__device__ __forceinline__ void split_tf32(float f, uint32_t& hi, uint32_t& lo) {
    asm("cvt.rna.tf32.f32 %0, %1;" : "=r"(hi) : "f"(f));
    float lf = f - __uint_as_float(hi);
    asm("cvt.rna.tf32.f32 %0, %1;" : "=r"(lo) : "f"(lf));
}

// k-permutation: (b[k], b[k+4]) / (a[k], a[k+4]) become adjacent -> LDS.64 pairs
__device__ __forceinline__ int permk(int k) {
    return (k & ~7) | ((k & 3) << 1) | ((k >> 2) & 1);
}

__global__ void k_wsplit(const float* __restrict__ w) {
    int i = blockIdx.x * blockDim.x + threadIdx.x;
    if (i >= WTOT) return;
    uint32_t hi, lo;
    split_tf32(w[i], hi, lo);
    int d = (i & ~(MAXF - 1)) | permk(i & (MAXF - 1));
    g_wh[d] = __uint_as_float(hi);
    g_wl[d] = __uint_as_float(lo);
}

__device__ __forceinline__ void mma8(float* c, const uint32_t* a, const uint32_t* b) {
    asm volatile(
        "mma.sync.aligned.m16n8k8.row.col.f32.tf32.tf32.f32 "
        "{%0,%1,%2,%3}, {%4,%5,%6,%7}, {%8,%9}, {%0,%1,%2,%3};\n"
        : "+f"(c[0]), "+f"(c[1]), "+f"(c[2]), "+f"(c[3])
        : "r"(a[0]), "r"(a[1]), "r"(a[2]), "r"(a[3]), "r"(b[0]), "r"(b[1]));
}

__device__ __forceinline__ void cpa16(void* sptr, const void* gptr) {
    uint32_t s = (uint32_t)__cvta_generic_to_shared(sptr);
    asm volatile("cp.async.cg.shared.global [%0], [%1], 16;\n" :: "r"(s), "l"(gptr) : "memory");
}
#define CP_COMMIT() asm volatile("cp.async.commit_group;\n" ::: "memory")
#define CP_WAIT0()  asm volatile("cp.async.wait_group 0;\n" ::: "memory")
#define CP_WAIT1()  asm volatile("cp.async.wait_group 1;\n" ::: "memory")

// ---------------- templated expert GEMM --------------------------------------------------
// BM=64 rows. 8 warps = 4 over M x 2 over N; each warp one m16 tile x NF n8 tiles.
// B is pre-split (hi/lo planes, k-permuted) in global -> smem via cp.async; NO runtime
// B splits. AREG (K<=32): A split to registers once. Otherwise A split once per block
// into k-permuted hi/lo smem; inner loop A access = 2x LDS.64 per half.
template <int K, bool AREG, int BN>
__device__ __forceinline__ void gemm_expert(
    int row0,
    const float* __restrict__ x,
    const float* __restrict__ wh,    // g_wh + e*OUTF*MAXF
    const float* __restrict__ wl,
    const float* __restrict__ be,
    float* __restrict__ out,
    float* sm)
{
    constexpr int  ldsA = AREG ? (K + 4) : (K + 8);   // scalar-read vs LDS.64-read strides
    constexpr int  ldsB = (K <= 16) ? 24 : (K + 8);   // ldsB % 32 in {24, 8}: conflict-free LDS.64
    constexpr int  kq   = K >> 2;
    constexpr int  KS   = K / 8;
    constexpr int  NT   = OUTF / BN;
    constexpr int  NF   = BN / 16;                    // n8 frags per warp (2 N-warps)
    constexpr bool DB   = (K <= 64);                  // double-buffered B
    constexpr int  LOGK = (K == 8) ? 3 : (K == 16) ? 4 : (K == 32) ? 5 : (K == 64) ? 6 : 7;
    constexpr int  BUFS = DB ? 2 : 1;
    constexpr int  BSZ  = 2 * BN * ldsB;              // hi+lo planes per buffer (floats)

    float* sA  = sm;                                  // AREG: raw [BM][ldsA]; else hi [BM][ldsA]
    float* sAl = sm + BM * ldsA;                      // (non-AREG only) lo plane
    float* sB  = sm + (AREG ? 1 : 2) * BM * ldsA;     // BUFS x (hi plane, lo plane)

    const int tx = threadIdx.x;

    // ---- B tile loader: copies pre-split hi+lo rows (already k-permuted) ----
    auto load_B = [&](float* buf, int nt) {
        const size_t nb = (size_t)nt * BN;
        #pragma unroll
        for (int i = tx; i < BN * kq; i += 256) {
            int r = i / kq, c = (i % kq) << 2;
            cpa16(buf + r * ldsB + c,             wh + (nb + r) * MAXF + c);
            cpa16(buf + BN * ldsB + r * ldsB + c, wl + (nb + r) * MAXF + c);
        }
    };

    // ---- prologue ----
    if (AREG) {
        // group0: raw A + B(0); group1: B(1)
        #pragma unroll
        for (int i = tx; i < BM * kq; i += 256) {
            int r = i / kq, c = (i % kq) << 2;
            int tok = g_rows[row0 + r];
            tok = tok < 0 ? 0 : tok;
            cpa16(sA + r * ldsA + c, x + (size_t)tok * MAXF + c);
        }
        load_B(sB, 0);
        CP_COMMIT();
        load_B(sB + BSZ, 1);
        CP_COMMIT();
    } else {
        // stage raw A in the B region, split to permuted hi/lo smem, then start B
        #pragma unroll
        for (int i = tx; i < BM * kq; i += 256) {
            int r = i / kq, c = (i % kq) << 2;
            int tok = g_rows[row0 + r];
            tok = tok < 0 ? 0 : tok;
            cpa16(sB + r * K + c, x + (size_t)tok * MAXF + c);
        }
        CP_COMMIT();
        CP_WAIT0();
        __syncthreads();
        #pragma unroll 4
        for (int i = tx; i < BM * K; i += 256) {
            int r = i >> LOGK, k = i & (K - 1);
            uint32_t hi, lo;
            split_tf32(sB[r * K + k], hi, lo);
            int p = permk(k);
            sA [r * ldsA + p] = __uint_as_float(hi);
            sAl[r * ldsA + p] = __uint_as_float(lo);
        }
        __syncthreads();
        load_B(sB, 0);
        CP_COMMIT();
        if (DB) { load_B(sB + BSZ, 1); CP_COMMIT(); }
    }

    const int warp = tx >> 5, lane = tx & 31;
    const int wm = warp & 3, wn = warp >> 2;          // 4 M-warps x 2 N-warps
    const int grp = lane >> 2, qid = lane & 3;

    const int t0 = g_rows[row0 + wm * 16 + grp];
    const int t1 = g_rows[row0 + wm * 16 + grp + 8];

    uint32_t rah[AREG ? KS : 1][4], ral[AREG ? KS : 1][4];
    const float* aH = sA  + (wm * 16 + grp) * ldsA + qid * 2;  // non-AREG LDS.64 base
    const float* aL = sAl + (wm * 16 + grp) * ldsA + qid * 2;

    for (int nt = 0; nt < NT; nt++) {
        if (DB) CP_WAIT1(); else CP_WAIT0();
        __syncthreads();
        const float* sBuf = DB ? (sB + (nt & 1) * BSZ) : sB;

        if (AREG && nt == 0) {
            const float* ap = sA + (wm * 16 + grp) * ldsA + qid;
            #pragma unroll
            for (int ks = 0; ks < KS; ks++) {
                split_tf32(ap[ks * 8],                rah[ks][0], ral[ks][0]);
                split_tf32(ap[ks * 8 + 8 * ldsA],     rah[ks][1], ral[ks][1]);
                split_tf32(ap[ks * 8 + 4],            rah[ks][2], ral[ks][2]);
                split_tf32(ap[ks * 8 + 8 * ldsA + 4], rah[ks][3], ral[ks][3]);
            }
        }

        // split accumulators -> independent MMA chains
        float c_hh[NF][4] = {}, c_lh[NF][4] = {}, c_hl[NF][4] = {};

        #pragma unroll
        for (int ks = 0; ks < KS; ks++) {
            uint32_t ah[4], al[4];
            if (AREG) {
                #pragma unroll
                for (int j = 0; j < 4; j++) { ah[j] = rah[ks][j]; al[j] = ral[ks][j]; }
            } else {
                uint2 h0 = *(const uint2*)(aH + ks * 8);
                uint2 h1 = *(const uint2*)(aH + ks * 8 + 8 * ldsA);
                uint2 l0 = *(const uint2*)(aL + ks * 8);
                uint2 l1 = *(const uint2*)(aL + ks * 8 + 8 * ldsA);
                ah[0] = h0.x; ah[1] = h1.x; ah[2] = h0.y; ah[3] = h1.y;
                al[0] = l0.x; al[1] = l1.x; al[2] = l0.y; al[3] = l1.y;
            }
            #pragma unroll
            for (int nf = 0; nf < NF; nf++) {
                const float* bp = sBuf + (wn * (BN / 2) + nf * 8 + grp) * ldsB + ks * 8 + qid * 2;
                uint2 bh2 = *(const uint2*)bp;
                uint2 bl2 = *(const uint2*)(bp + BN * ldsB);
                uint32_t bh[2] = {bh2.x, bh2.y};
                uint32_t bl[2] = {bl2.x, bl2.y};
                mma8(c_hh[nf], ah, bh);
                mma8(c_lh[nf], al, bh);
                mma8(c_hl[nf], ah, bl);
            }
        }

        // ---- scatter epilogue: merge partial sums + bias ----
        const int n0 = nt * BN + wn * (BN / 2);
        #pragma unroll
        for (int nf = 0; nf < NF; nf++) {
            int c = n0 + nf * 8 + (qid << 1);
            float2 bv = *(const float2*)(be + c);
            if (t0 >= 0) {
                float2 o = make_float2(c_hh[nf][0] + c_lh[nf][0] + c_hl[nf][0] + bv.x,
                                       c_hh[nf][1] + c_lh[nf][1] + c_hl[nf][1] + bv.y);
                *(float2*)(out + (size_t)t0 * OUTF + c) = o;
            }
            if (t1 >= 0) {
                float2 o = make_float2(c_hh[nf][2] + c_lh[nf][2] + c_hl[nf][2] + bv.x,
                                       c_hh[nf][3] + c_lh[nf][3] + c_hl[nf][3] + bv.y);
                *(float2*)(out + (size_t)t1 * OUTF + c) = o;
            }
        }

        __syncthreads();
        if (DB) {
            if (nt + 2 < NT) load_B(sB + (nt & 1) * BSZ, nt + 2);
            CP_COMMIT();                              // keep wait_group(1) invariant
        } else {
            if (nt + 1 < NT) { load_B(sB, nt + 1); CP_COMMIT(); }
        }
    }
}

__global__ void __launch_bounds__(256, 2)
k_gemm(const float* __restrict__ x, const float* __restrict__ bias, float* __restrict__ out) {
    extern __shared__ float sm[];
    // reversed order: heavy K=128 blocks (highest rows) scheduled FIRST
    const int total = g_offsets[NUM_E];
    const int row0  = total - (int)(blockIdx.x + 1) * BM;
    if (row0 < 0) return;

    int e = 0;
    #pragma unroll
    for (int i = 1; i < NUM_E; i++) e += (row0 >= g_offsets[i]);

    const float* wh = g_wh + (size_t)e * OUTF * MAXF;
    const float* wl = g_wl + (size_t)e * OUTF * MAXF;
    const float* be = bias + e * OUTF;

    switch (e) {
        case 0:  gemm_expert<  8, true,  64>(row0, x, wh, wl, be, out, sm); break;
        case 1:  gemm_expert< 16, true,  64>(row0, x, wh, wl, be, out, sm); break;
        case 2:  gemm_expert< 32, true,  64>(row0, x, wh, wl, be, out, sm); break;
        case 3:  gemm_expert< 64, false, 32>(row0, x, wh, wl, be, out, sm); break;
        default: gemm_expert<128, false, 32>(row0, x, wh, wl, be, out, sm); break;
    }
}

// ---------------- launch ----------------
extern "C" void kernel_launch(void* const* d_in, const int* in_sizes, int n_in,
                              void* d_out, int out_size) {
    (void)in_sizes; (void)n_in; (void)out_size;
    const float* x    = (const float*)d_in[0];
    const int*   feat = (const int*)d_in[1];
    const float* w    = (const float*)d_in[2];
    const float* b    = (const float*)d_in[3];
    float*       out  = (float*)d_out;

    cudaFuncSetAttribute(k_gemm, cudaFuncAttributeMaxDynamicSharedMemorySize, SMEM_BYTES);

    k_wsplit <<<(WTOT + 255) / 256, 256>>>(w);
    k_count  <<<(NTOK + 255) / 256, 256>>>(feat);
    k_offsets<<<1, 256>>>();
    k_scatter<<<(NTOK + 255) / 256, 256>>>(feat);
    k_gemm   <<<MAX_MTILES, 256, SMEM_BYTES>>>(x, b, out);
}